// round 1
// baseline (speedup 1.0000x reference)
#include <cuda_runtime.h>

#define INC   64
#define OUTC  64
#define KOFF  27
#define TILE_P 64
#define FSTRIDE 68   // keeps 16B alignment for LDS.128 a-column reads
#define BN_EPS 1e-5f

__device__ int   g_counts[KOFF];
__device__ float g_sum[OUTC];
__device__ float g_sumsq[OUTC];

// ---------- packed fp32x2 helpers (Blackwell FFMA2 path) ----------
static __device__ __forceinline__ unsigned long long pack2(float lo, float hi) {
    unsigned long long r;
    asm("mov.b64 %0, {%1, %2};" : "=l"(r) : "f"(lo), "f"(hi));
    return r;
}
static __device__ __forceinline__ unsigned long long pack_dup(float x) {
    unsigned long long r;
    asm("mov.b64 %0, {%1, %1};" : "=l"(r) : "f"(x));
    return r;
}
static __device__ __forceinline__ void unpack2(unsigned long long v, float& lo, float& hi) {
    asm("mov.b64 {%0, %1}, %2;" : "=f"(lo), "=f"(hi) : "l"(v));
}
static __device__ __forceinline__ unsigned long long fma2(
    unsigned long long a, unsigned long long b, unsigned long long c) {
    unsigned long long d;
    asm("fma.rn.f32x2 %0, %1, %2, %3;" : "=l"(d) : "l"(a), "l"(b), "l"(c));
    return d;
}

// ---------- K0a: per-offset valid-pair counts (mask rows are 1-prefixes) ----------
__global__ void k_init(const float* __restrict__ mask, int n) {
    int t = threadIdx.x;
    if (t < OUTC) { g_sum[t] = 0.f; g_sumsq[t] = 0.f; }
    if (t < KOFF) {
        const float* m = mask + (size_t)t * n;
        int lo = 0, hi = n;
        while (lo < hi) {
            int mid = (lo + hi) >> 1;
            if (m[mid] > 0.5f) lo = mid + 1; else hi = mid;
        }
        g_counts[t] = lo;
    }
}

// ---------- K0b: zero the (poisoned) output accumulator ----------
__global__ void k_zero(float4* __restrict__ out, int total4) {
    int i = blockIdx.x * blockDim.x + threadIdx.x;
    if (i < total4) out[i] = make_float4(0.f, 0.f, 0.f, 0.f);
}

// ---------- K1: gather -> 64x64x64 tile GEMM (fp32x2) -> vector-red scatter ----------
__global__ __launch_bounds__(128)
void k_gemm(const float* __restrict__ feats, const float* __restrict__ W,
            const int* __restrict__ in_idx, const int* __restrict__ out_idx,
            float* __restrict__ out, int n)
{
    const int k    = blockIdx.y;
    const int base = blockIdx.x * TILE_P;
    const int cnt  = g_counts[k];
    if (base >= cnt) return;                  // skip padded region entirely
    const int np = min(TILE_P, cnt - base);

    __shared__ float Wsm[INC * OUTC];         // [inc][outc]
    __shared__ float Fsm[INC * FSTRIDE];      // transposed: [inc][pair]

    const int tid = threadIdx.x;

    // load W[k] (16KB) into smem, float4 copies
    {
        const float4* Wg  = (const float4*)(W + (size_t)k * INC * OUTC);
        float4*       Ws4 = (float4*)Wsm;
        #pragma unroll
        for (int i = tid; i < INC * OUTC / 4; i += 128) Ws4[i] = Wg[i];
    }

    // gather 64 feats rows, stored transposed; zero rows past np
    {
        const int p    = tid >> 1;
        const int half = (tid & 1) * 32;
        const size_t kbase = (size_t)k * n + base;
        if (p < np) {
            const int src = in_idx[kbase + p];
            const float4* fr = (const float4*)(feats + (size_t)src * INC + half);
            #pragma unroll
            for (int j = 0; j < 8; j++) {
                float4 v = fr[j];
                int c = half + j * 4;
                Fsm[(c + 0) * FSTRIDE + p] = v.x;
                Fsm[(c + 1) * FSTRIDE + p] = v.y;
                Fsm[(c + 2) * FSTRIDE + p] = v.z;
                Fsm[(c + 3) * FSTRIDE + p] = v.w;
            }
        } else {
            #pragma unroll
            for (int j = 0; j < 8; j++) {
                int c = half + j * 4;
                Fsm[(c + 0) * FSTRIDE + p] = 0.f;
                Fsm[(c + 1) * FSTRIDE + p] = 0.f;
                Fsm[(c + 2) * FSTRIDE + p] = 0.f;
                Fsm[(c + 3) * FSTRIDE + p] = 0.f;
            }
        }
    }
    __syncthreads();

    // micro-tile: 4 pairs x 8 outc per thread, outc packed 2-wide in f32x2
    const int pt = tid >> 3;   // 0..15
    const int ot = tid & 7;    // 0..7
    unsigned long long acc[4][4];
    #pragma unroll
    for (int i = 0; i < 4; i++)
        #pragma unroll
        for (int j = 0; j < 4; j++) acc[i][j] = 0ull;   // bits of (+0.f, +0.f)

    #pragma unroll 8
    for (int kk = 0; kk < INC; kk++) {
        float4 av = *(const float4*)&Fsm[kk * FSTRIDE + pt * 4];
        float4 b0 = *(const float4*)&Wsm[kk * OUTC + ot * 8];
        float4 b1 = *(const float4*)&Wsm[kk * OUTC + ot * 8 + 4];
        unsigned long long bb0 = pack2(b0.x, b0.y);
        unsigned long long bb1 = pack2(b0.z, b0.w);
        unsigned long long bb2 = pack2(b1.x, b1.y);
        unsigned long long bb3 = pack2(b1.z, b1.w);
        unsigned long long a0 = pack_dup(av.x);
        unsigned long long a1 = pack_dup(av.y);
        unsigned long long a2 = pack_dup(av.z);
        unsigned long long a3 = pack_dup(av.w);
        acc[0][0] = fma2(a0, bb0, acc[0][0]);
        acc[0][1] = fma2(a0, bb1, acc[0][1]);
        acc[0][2] = fma2(a0, bb2, acc[0][2]);
        acc[0][3] = fma2(a0, bb3, acc[0][3]);
        acc[1][0] = fma2(a1, bb0, acc[1][0]);
        acc[1][1] = fma2(a1, bb1, acc[1][1]);
        acc[1][2] = fma2(a1, bb2, acc[1][2]);
        acc[1][3] = fma2(a1, bb3, acc[1][3]);
        acc[2][0] = fma2(a2, bb0, acc[2][0]);
        acc[2][1] = fma2(a2, bb1, acc[2][1]);
        acc[2][2] = fma2(a2, bb2, acc[2][2]);
        acc[2][3] = fma2(a2, bb3, acc[2][3]);
        acc[3][0] = fma2(a3, bb0, acc[3][0]);
        acc[3][1] = fma2(a3, bb1, acc[3][1]);
        acc[3][2] = fma2(a3, bb2, acc[3][2]);
        acc[3][3] = fma2(a3, bb3, acc[3][3]);
    }

    // scatter: 2 x red.global.add.v4.f32 per valid pair per thread
    const size_t kbase = (size_t)k * n + base;
    #pragma unroll
    for (int i = 0; i < 4; i++) {
        int p = pt * 4 + i;
        if (p < np) {
            int dst = out_idx[kbase + p];
            float* o = out + (size_t)dst * OUTC + ot * 8;
            float f0, f1, f2, f3, f4, f5, f6, f7;
            unpack2(acc[i][0], f0, f1);
            unpack2(acc[i][1], f2, f3);
            unpack2(acc[i][2], f4, f5);
            unpack2(acc[i][3], f6, f7);
            asm volatile("red.global.add.v4.f32 [%0], {%1,%2,%3,%4};"
                         :: "l"(o), "f"(f0), "f"(f1), "f"(f2), "f"(f3) : "memory");
            asm volatile("red.global.add.v4.f32 [%0+16], {%1,%2,%3,%4};"
                         :: "l"(o), "f"(f4), "f"(f5), "f"(f6), "f"(f7) : "memory");
        }
    }
}

// ---------- K2: per-channel sum / sumsq ----------
__global__ void k_stats(const float* __restrict__ out, int n) {
    const int c = threadIdx.x & 63;
    const int g = threadIdx.x >> 6;
    float s = 0.f, s2 = 0.f;
    for (int r = blockIdx.x * 4 + g; r < n; r += gridDim.x * 4) {
        float v = out[(size_t)r * 64 + c];
        s  += v;
        s2 += v * v;
    }
    atomicAdd(&g_sum[c],   s);
    atomicAdd(&g_sumsq[c], s2);
}

// ---------- K3: BatchNorm (population stats) + ReLU, in place ----------
__global__ void k_bn(float4* __restrict__ out,
                     const float* __restrict__ gamma, const float* __restrict__ beta,
                     int total4, float invN)
{
    for (int i = blockIdx.x * blockDim.x + threadIdx.x; i < total4;
         i += gridDim.x * blockDim.x) {
        const int cg = (i & 15) * 4;       // channel of .x within the 64-wide row
        float4 v = out[i];
        float r[4] = {v.x, v.y, v.z, v.w};
        #pragma unroll
        for (int j = 0; j < 4; j++) {
            int c = cg + j;
            float mean = g_sum[c] * invN;
            float var  = g_sumsq[c] * invN - mean * mean;
            float s = rsqrtf(var + BN_EPS) * gamma[c];
            float y = (r[j] - mean) * s + beta[c];
            r[j] = y > 0.f ? y : 0.f;
        }
        out[i] = make_float4(r[0], r[1], r[2], r[3]);
    }
}

// ---------- launch ----------
extern "C" void kernel_launch(void* const* d_in, const int* in_sizes, int n_in,
                              void* d_out, int out_size)
{
    const float* feats   = (const float*)d_in[0];
    const float* W       = (const float*)d_in[1];
    const float* gamma   = (const float*)d_in[2];
    const float* beta    = (const float*)d_in[3];
    const float* mask    = (const float*)d_in[4];
    const int*   in_idx  = (const int*)d_in[5];
    const int*   out_idx = (const int*)d_in[6];
    float*       out     = (float*)d_out;

    const int n = in_sizes[0] / INC;
    const int total4 = (n * OUTC) / 4;

    k_init<<<1, 64>>>(mask, n);
    k_zero<<<(total4 + 255) / 256, 256>>>((float4*)out, total4);

    dim3 grid((n + TILE_P - 1) / TILE_P, KOFF);
    k_gemm<<<grid, 128>>>(feats, W, in_idx, out_idx, out, n);

    k_stats<<<592, 256>>>(out, n);
    k_bn<<<2048, 256>>>((float4*)out, gamma, beta, total4, 1.0f / (float)n);
}

// round 2
// speedup vs baseline: 1.0092x; 1.0092x over previous
#include <cuda_runtime.h>

#define INC   64
#define OUTC  64
#define KOFF  27
#define TILE_P 64
#define BN_EPS 1e-5f

typedef unsigned long long ull;

__device__ int   g_counts[KOFF];
__device__ float g_sum[OUTC];
__device__ float g_sumsq[OUTC];

// ---------- packed fp32x2 helpers ----------
static __device__ __forceinline__ ull fma2(ull a, ull b, ull c) {
    ull d;
    asm("fma.rn.f32x2 %0, %1, %2, %3;" : "=l"(d) : "l"(a), "l"(b), "l"(c));
    return d;
}
static __device__ __forceinline__ void unpack2(ull v, float& lo, float& hi) {
    asm("mov.b64 {%0, %1}, %2;" : "=f"(lo), "=f"(hi) : "l"(v));
}

// ---------- K0a: per-offset valid-pair counts (mask rows are 1-prefixes) ----------
__global__ void k_init(const float* __restrict__ mask, int n) {
    int t = threadIdx.x;
    if (t < OUTC) { g_sum[t] = 0.f; g_sumsq[t] = 0.f; }
    if (t < KOFF) {
        const float* m = mask + (size_t)t * n;
        int lo = 0, hi = n;
        while (lo < hi) {
            int mid = (lo + hi) >> 1;
            if (m[mid] > 0.5f) lo = mid + 1; else hi = mid;
        }
        g_counts[t] = lo;
    }
}

// ---------- K0b: zero the (poisoned) output accumulator ----------
__global__ void k_zero(float4* __restrict__ out, int total4) {
    for (int i = blockIdx.x * blockDim.x + threadIdx.x; i < total4;
         i += gridDim.x * blockDim.x)
        out[i] = make_float4(0.f, 0.f, 0.f, 0.f);
}

// ---------- K1: gather -> 64x64x64 tile GEMM (MOV-free fp32x2) -> red.v4 scatter ----------
__global__ __launch_bounds__(128)
void k_gemm(const float* __restrict__ feats, const float* __restrict__ W,
            const int* __restrict__ in_idx, const int* __restrict__ out_idx,
            float* __restrict__ out, int n)
{
    const int k    = blockIdx.y;
    const int base = blockIdx.x * TILE_P;
    const int cnt  = g_counts[k];
    if (base >= cnt) return;
    const int np = min(TILE_P, cnt - base);

    __shared__ float Wd[INC * 2 * OUTC];   // duplicated: Wd[kk][2c], Wd[kk][2c+1] = W[k][kk][c]  (32KB)
    __shared__ float Fsm[INC * TILE_P];    // transposed: Fsm[kk][p]                              (16KB)

    const int tid = threadIdx.x;

    // load W[k] (16KB), write duplicated (32KB)
    {
        const float4* Wg = (const float4*)(W + (size_t)k * INC * OUTC);
        #pragma unroll
        for (int i = tid; i < INC * OUTC / 4; i += 128) {
            float4 v = Wg[i];
            int kk = i >> 4;          // 16 float4 per kk row
            int cq = i & 15;          // 4-col group
            float4* dst = (float4*)&Wd[kk * 128 + cq * 8];
            dst[0] = make_float4(v.x, v.x, v.y, v.y);
            dst[1] = make_float4(v.z, v.z, v.w, v.w);
        }
    }

    // gather 64 feats rows into transposed smem (lane p -> bank p, conflict-free)
    const size_t kbase = (size_t)k * n + base;
    if (tid < TILE_P) {
        const int p = tid;
        if (p < np) {
            const int src = in_idx[kbase + p];
            const float4* fr = (const float4*)(feats + (size_t)src * INC);
            #pragma unroll
            for (int j = 0; j < 16; j++) {
                float4 v = fr[j];
                Fsm[(4 * j + 0) * TILE_P + p] = v.x;
                Fsm[(4 * j + 1) * TILE_P + p] = v.y;
                Fsm[(4 * j + 2) * TILE_P + p] = v.z;
                Fsm[(4 * j + 3) * TILE_P + p] = v.w;
            }
        } else {
            #pragma unroll
            for (int j = 0; j < INC; j++) Fsm[j * TILE_P + p] = 0.f;
        }
    }
    __syncthreads();

    // micro-tile: 8 pairs (pg) x 4 scalar cols (cg). acc[c][pp]: pp spans pair-pairs.
    const int pg = tid >> 4;   // 0..7
    const int cg = tid & 15;   // 0..15
    ull acc[4][4];
    #pragma unroll
    for (int c = 0; c < 4; c++)
        #pragma unroll
        for (int pp = 0; pp < 4; pp++) acc[c][pp] = 0ull;

    const float* fptr = &Fsm[pg * 8];
    const float* wptr = &Wd[cg * 8];

    #pragma unroll 8
    for (int kk = 0; kk < INC; kk++) {
        // a: 8 pair values as 4 f32x2 (direct LDS.128, no packing)
        ulonglong2 a01 = *(const ulonglong2*)(fptr + kk * TILE_P);
        ulonglong2 a23 = *(const ulonglong2*)(fptr + kk * TILE_P + 4);
        // b: 4 duplicated col values as 4 f32x2 (direct LDS.128, no packing)
        ulonglong2 b01 = *(const ulonglong2*)(wptr + kk * 128);
        ulonglong2 b23 = *(const ulonglong2*)(wptr + kk * 128 + 4);

        acc[0][0] = fma2(a01.x, b01.x, acc[0][0]);
        acc[0][1] = fma2(a01.y, b01.x, acc[0][1]);
        acc[0][2] = fma2(a23.x, b01.x, acc[0][2]);
        acc[0][3] = fma2(a23.y, b01.x, acc[0][3]);
        acc[1][0] = fma2(a01.x, b01.y, acc[1][0]);
        acc[1][1] = fma2(a01.y, b01.y, acc[1][1]);
        acc[1][2] = fma2(a23.x, b01.y, acc[1][2]);
        acc[1][3] = fma2(a23.y, b01.y, acc[1][3]);
        acc[2][0] = fma2(a01.x, b23.x, acc[2][0]);
        acc[2][1] = fma2(a01.y, b23.x, acc[2][1]);
        acc[2][2] = fma2(a23.x, b23.x, acc[2][2]);
        acc[2][3] = fma2(a23.y, b23.x, acc[2][3]);
        acc[3][0] = fma2(a01.x, b23.y, acc[3][0]);
        acc[3][1] = fma2(a01.y, b23.y, acc[3][1]);
        acc[3][2] = fma2(a23.x, b23.y, acc[3][2]);
        acc[3][3] = fma2(a23.y, b23.y, acc[3][3]);
    }

    // scatter: thread owns 4 contiguous cols -> one red.v4 per valid pair
    #pragma unroll
    for (int i = 0; i < 8; i++) {
        const int p = pg * 8 + i;
        if (p < np) {
            const int pp = i >> 1;
            float c0l, c0h, c1l, c1h, c2l, c2h, c3l, c3h;
            unpack2(acc[0][pp], c0l, c0h);
            unpack2(acc[1][pp], c1l, c1h);
            unpack2(acc[2][pp], c2l, c2h);
            unpack2(acc[3][pp], c3l, c3h);
            float f0 = (i & 1) ? c0h : c0l;
            float f1 = (i & 1) ? c1h : c1l;
            float f2 = (i & 1) ? c2h : c2l;
            float f3 = (i & 1) ? c3h : c3l;
            const int dst = out_idx[kbase + p];
            float* o = out + (size_t)dst * OUTC + cg * 4;
            asm volatile("red.global.add.v4.f32 [%0], {%1,%2,%3,%4};"
                         :: "l"(o), "f"(f0), "f"(f1), "f"(f2), "f"(f3) : "memory");
        }
    }
}

// ---------- K2: per-channel sum / sumsq (MLP=4, channel fixed per thread) ----------
__global__ __launch_bounds__(256)
void k_stats(const float4* __restrict__ out4, int total4) {
    const int tid = threadIdx.x;
    const int cg  = (tid & 15) * 4;     // fixed channel group: stride % 16 == 0
    float s0 = 0.f, s1 = 0.f, s2 = 0.f, s3 = 0.f;
    float q0 = 0.f, q1 = 0.f, q2 = 0.f, q3 = 0.f;

    const int stride = gridDim.x * 256;
    int i = blockIdx.x * 256 + tid;
    for (; i + 3 * stride < total4; i += 4 * stride) {
        float4 v0 = out4[i];
        float4 v1 = out4[i + stride];
        float4 v2 = out4[i + 2 * stride];
        float4 v3 = out4[i + 3 * stride];
        s0 += v0.x + v1.x + v2.x + v3.x;
        s1 += v0.y + v1.y + v2.y + v3.y;
        s2 += v0.z + v1.z + v2.z + v3.z;
        s3 += v0.w + v1.w + v2.w + v3.w;
        q0 += v0.x*v0.x + v1.x*v1.x + v2.x*v2.x + v3.x*v3.x;
        q1 += v0.y*v0.y + v1.y*v1.y + v2.y*v2.y + v3.y*v3.y;
        q2 += v0.z*v0.z + v1.z*v1.z + v2.z*v2.z + v3.z*v3.z;
        q3 += v0.w*v0.w + v1.w*v1.w + v2.w*v2.w + v3.w*v3.w;
    }
    for (; i < total4; i += stride) {
        float4 v = out4[i];
        s0 += v.x; s1 += v.y; s2 += v.z; s3 += v.w;
        q0 += v.x*v.x; q1 += v.y*v.y; q2 += v.z*v.z; q3 += v.w*v.w;
    }

    __shared__ float ssum[OUTC];
    __shared__ float ssq[OUTC];
    if (tid < OUTC) { ssum[tid] = 0.f; ssq[tid] = 0.f; }
    __syncthreads();
    atomicAdd(&ssum[cg + 0], s0); atomicAdd(&ssq[cg + 0], q0);
    atomicAdd(&ssum[cg + 1], s1); atomicAdd(&ssq[cg + 1], q1);
    atomicAdd(&ssum[cg + 2], s2); atomicAdd(&ssq[cg + 2], q2);
    atomicAdd(&ssum[cg + 3], s3); atomicAdd(&ssq[cg + 3], q3);
    __syncthreads();
    if (tid < OUTC) {
        atomicAdd(&g_sum[tid],   ssum[tid]);
        atomicAdd(&g_sumsq[tid], ssq[tid]);
    }
}

// ---------- K3: BatchNorm + ReLU, channel constants hoisted ----------
__global__ __launch_bounds__(256)
void k_bn(float4* __restrict__ out,
          const float* __restrict__ gamma, const float* __restrict__ beta,
          int total4, float invN)
{
    const int tid = threadIdx.x;
    const int cg  = (tid & 15) * 4;     // fixed channels for this thread
    float mean[4], scl[4], bet[4];
    #pragma unroll
    for (int j = 0; j < 4; j++) {
        int c = cg + j;
        float m = g_sum[c] * invN;
        float var = g_sumsq[c] * invN - m * m;
        mean[j] = m;
        scl[j] = rsqrtf(var + BN_EPS) * gamma[c];
        bet[j] = beta[c];
    }
    const int stride = gridDim.x * 256;
    for (int i = blockIdx.x * 256 + tid; i < total4; i += stride) {
        float4 v = out[i];
        v.x = fmaxf((v.x - mean[0]) * scl[0] + bet[0], 0.f);
        v.y = fmaxf((v.y - mean[1]) * scl[1] + bet[1], 0.f);
        v.z = fmaxf((v.z - mean[2]) * scl[2] + bet[2], 0.f);
        v.w = fmaxf((v.w - mean[3]) * scl[3] + bet[3], 0.f);
        out[i] = v;
    }
}

// ---------- launch ----------
extern "C" void kernel_launch(void* const* d_in, const int* in_sizes, int n_in,
                              void* d_out, int out_size)
{
    const float* feats   = (const float*)d_in[0];
    const float* W       = (const float*)d_in[1];
    const float* gamma   = (const float*)d_in[2];
    const float* beta    = (const float*)d_in[3];
    const float* mask    = (const float*)d_in[4];
    const int*   in_idx  = (const int*)d_in[5];
    const int*   out_idx = (const int*)d_in[6];
    float*       out     = (float*)d_out;

    const int n = in_sizes[0] / INC;
    const int total4 = (n * OUTC) / 4;

    k_init<<<1, 64>>>(mask, n);
    k_zero<<<2048, 256>>>((float4*)out, total4);

    dim3 grid((n + TILE_P - 1) / TILE_P, KOFF);
    k_gemm<<<grid, 128>>>(feats, W, in_idx, out_idx, out, n);

    k_stats<<<1184, 256>>>((const float4*)out, total4);
    k_bn<<<2048, 256>>>((float4*)out, gamma, beta, total4, 1.0f / (float)n);
}